// round 11
// baseline (speedup 1.0000x reference)
#include <cuda_runtime.h>
#include <cuda_bf16.h>
#include <math_constants.h>
#include <cstdint>

#define BATCH 4
#define SEQ 4096
#define DMODEL 1024
#define DHEAD 128
#define MROWS (BATCH*SEQ)   // 16384

#define CHUNK 16            // max KV tiles (of 64 keys) per work unit
#define NUNITS 320          // 4 batches * sum_ib ceil((2ib+2)/16) = 4*80
#define NSLOTS 512          // (b*32+ib)*4 + c, c < 4

#define QSCALEF (1.4426950408889634f * 0.08838834764831845f)  // log2e/sqrt(128)

// Scratch (device globals: no allocations allowed).
// g_Q/g_K/g_V hold tf32 bit patterns (cvt.rna applied in proj epilogue;
// Q additionally pre-scaled by QSCALEF) so flash stages them with raw cp.async.
__device__ float g_Q[MROWS*DHEAD];
__device__ float g_K[MROWS*DHEAD];
__device__ float g_V[MROWS*DHEAD];
__device__ float g_pO[NSLOTS*128*DHEAD];   // un-normalized partial O per slot
__device__ float g_pm[NSLOTS*128];         // per-row running max (exp2 domain)
__device__ float g_pl[NSLOTS*128];         // per-row partial denom
__device__ int   g_ctr;                    // persistent-kernel work counter

__device__ __forceinline__ unsigned f2tf32(float x){
    unsigned y; asm("cvt.rna.tf32.f32 %0, %1;" : "=r"(y) : "f"(x)); return y;
}

__device__ __forceinline__ void mma_tf32(float* d,
    unsigned a0, unsigned a1, unsigned a2, unsigned a3,
    unsigned b0, unsigned b1)
{
    asm volatile(
        "mma.sync.aligned.m16n8k8.row.col.f32.tf32.tf32.f32 "
        "{%0,%1,%2,%3}, {%4,%5,%6,%7}, {%8,%9}, {%0,%1,%2,%3};"
        : "+f"(d[0]), "+f"(d[1]), "+f"(d[2]), "+f"(d[3])
        : "r"(a0), "r"(a1), "r"(a2), "r"(a3), "r"(b0), "r"(b1));
}

__device__ __forceinline__ uint32_t smem_u32(const void* p){
    uint32_t a;
    asm("{ .reg .u64 t; cvta.to.shared.u64 t, %1; cvt.u32.u64 %0, t; }"
        : "=r"(a) : "l"(p));
    return a;
}

// cp.async (Ampere+; supported on sm_100)
__device__ __forceinline__ void cpa16(uint32_t dst, const void* src){
    asm volatile("cp.async.cg.shared.global [%0], [%1], 16;"
        :: "r"(dst), "l"(src) : "memory");
}
#define CP_COMMIT  asm volatile("cp.async.commit_group;" ::: "memory")
#define CP_WAIT1   asm volatile("cp.async.wait_group 1;" ::: "memory")

// ============================================================================
// Projection: Y[16384,128] = X[16384,1024] @ W[128,1024]^T   (tf32 HMMA)
// Static-smem version (measured 153 us). Epilogue stores tf32 bit patterns;
// Q output is pre-scaled by QSCALEF.
// ============================================================================
#define PSTR 36   // smem stride (32 + 4): fragment loads bank-conflict-free

__global__ __launch_bounds__(256, 2) void proj_kernel(
    const float* __restrict__ q, const float* __restrict__ k, const float* __restrict__ v,
    const float* __restrict__ wq, const float* __restrict__ wk, const float* __restrict__ wv)
{
    __shared__ unsigned Xs[128*PSTR];
    __shared__ unsigned Ws[128*PSTR];

    const float* X; const float* W; float* Y;
    if (blockIdx.z == 0)      { X = q; W = wq; Y = g_Q; }
    else if (blockIdx.z == 1) { X = k; W = wk; Y = g_K; }
    else                      { X = v; W = wv; Y = g_V; }

    const int row0 = blockIdx.x * 128;
    const int tid  = threadIdx.x;
    const int wid  = tid >> 5;
    const int lane = tid & 31;
    const int g    = lane >> 2;
    const int t    = lane & 3;
    const int wr   = (wid >> 1) * 32;
    const int wc   = (wid & 1) * 64;

    float acc[2][8][4] = {};

    for (int k0 = 0; k0 < DMODEL; k0 += 32) {
        #pragma unroll
        for (int i = 0; i < 4; i++) {
            int e = tid + i * 256;
            int r = e >> 3, c = e & 7;
            float4 x = *(const float4*)&X[(size_t)(row0 + r) * DMODEL + k0 + c*4];
            float4 w = *(const float4*)&W[(size_t)r * DMODEL + k0 + c*4];
            uint4 xt = { f2tf32(x.x), f2tf32(x.y), f2tf32(x.z), f2tf32(x.w) };
            uint4 wt = { f2tf32(w.x), f2tf32(w.y), f2tf32(w.z), f2tf32(w.w) };
            *(uint4*)&Xs[r*PSTR + c*4] = xt;
            *(uint4*)&Ws[r*PSTR + c*4] = wt;
        }
        __syncthreads();

        #pragma unroll
        for (int kt = 0; kt < 4; kt++) {
            unsigned a[2][4];
            #pragma unroll
            for (int mt = 0; mt < 2; mt++) {
                int r = wr + mt * 16;
                a[mt][0] = Xs[(r + g    )*PSTR + kt*8 + t];
                a[mt][1] = Xs[(r + g + 8)*PSTR + kt*8 + t];
                a[mt][2] = Xs[(r + g    )*PSTR + kt*8 + t + 4];
                a[mt][3] = Xs[(r + g + 8)*PSTR + kt*8 + t + 4];
            }
            #pragma unroll
            for (int nt = 0; nt < 8; nt++) {
                unsigned b0 = Ws[(wc + nt*8 + g)*PSTR + kt*8 + t];
                unsigned b1 = Ws[(wc + nt*8 + g)*PSTR + kt*8 + t + 4];
                mma_tf32(acc[0][nt], a[0][0], a[0][1], a[0][2], a[0][3], b0, b1);
                mma_tf32(acc[1][nt], a[1][0], a[1][1], a[1][2], a[1][3], b0, b1);
            }
        }
        __syncthreads();
    }

    // Epilogue: store tf32 bit patterns (Q pre-scaled)
    const float scale = (blockIdx.z == 0) ? QSCALEF : 1.0f;
    #pragma unroll
    for (int mt = 0; mt < 2; mt++) {
        int r = row0 + wr + mt*16 + g;
        #pragma unroll
        for (int nt = 0; nt < 8; nt++) {
            int c = wc + nt*8 + 2*t;
            float2 v0 = make_float2(__uint_as_float(f2tf32(acc[mt][nt][0]*scale)),
                                    __uint_as_float(f2tf32(acc[mt][nt][1]*scale)));
            float2 v1 = make_float2(__uint_as_float(f2tf32(acc[mt][nt][2]*scale)),
                                    __uint_as_float(f2tf32(acc[mt][nt][3]*scale)));
            *(float2*)&Y[(size_t)r * DHEAD + c]       = v0;
            *(float2*)&Y[(size_t)(r + 8) * DHEAD + c] = v1;
        }
    }
}

// ============================================================================
// Split-KV flash attention, causal. Persistent CTAs + LPT work units.
// cp.async double-buffered K/V staging; P kept in registers (shuffle
// re-fragmentation S-layout -> A-layout); no P smem.
// ============================================================================
#define QSTRW 132
#define KSTRW 132
#define VSTRW 136
#define QW (128*QSTRW)            // 16896 words
#define KW (64*KSTRW)             // 8448 words
#define VW (64*VSTRW)             // 8704 words
#define FLASH_SMEM ((QW + 2*(KW+VW)) * 4)   // 204800 B

__device__ __forceinline__ void decode_unit(int u, int& b, int& ib,
                                            int& j0, int& j1, int& slot)
{
    b = u & 3;
    int v = u >> 2;              // 0..79, descending-ib order (big units first)
    int acc = 0, ibb = 0, n = 1;
    #pragma unroll 1
    for (int i = 31; i >= 0; --i) {
        int jm = 2*i + 2;
        int ni = (jm + CHUNK - 1) / CHUNK;
        if (v < acc + ni) { ibb = i; n = ni; break; }
        acc += ni;
    }
    int c    = v - acc;
    int jmax = 2*ibb + 2;
    int len  = (jmax + n - 1) / n;
    j0 = c * len;
    j1 = min(jmax, j0 + len);
    ib = ibb;
    slot = ((b*32 + ibb) << 2) + c;
}

__global__ __launch_bounds__(256, 1) void flash_kernel()
{
    extern __shared__ unsigned sm[];
    unsigned* Qs = sm;
    unsigned* KsP[2] = { sm + QW,           sm + QW + KW + VW };
    unsigned* VsP[2] = { sm + QW + KW,      sm + QW + 2*KW + VW };
    __shared__ int s_unit;

    const uint32_t smb = smem_u32(sm);
    const uint32_t qbs = smb;
    const uint32_t kbs[2] = { smb + QW*4,          smb + (QW + KW + VW)*4 };
    const uint32_t vbs[2] = { smb + (QW + KW)*4,   smb + (QW + 2*KW + VW)*4 };

    const int tid  = threadIdx.x;
    const int wid  = tid >> 5;
    const int lane = tid & 31;
    const int g    = lane >> 2;
    const int t    = lane & 3;
    const int rA   = wid * 16 + g;   // local row (and rA+8)

    for (;;) {
        if (tid == 0) s_unit = atomicAdd(&g_ctr, 1);
        __syncthreads();             // broadcast; also fences prior unit's smem reads
        int u = s_unit;
        if (u >= NUNITS) break;

        int b, ib, j0, j1, slot;
        decode_unit(u, b, ib, j0, j1, slot);
        const int qrow0 = ib * 128;
        const float* Q = g_Q + (size_t)b * SEQ * DHEAD;
        const float* K = g_K + (size_t)b * SEQ * DHEAD;
        const float* V = g_V + (size_t)b * SEQ * DHEAD;

        // ---- async stage: Q + KV(j0) as group 0, KV(j0+1) as group 1 ----
        {
            const char* Qg = (const char*)(Q + (size_t)qrow0 * DHEAD);
            #pragma unroll
            for (int i = 0; i < 16; i++) {
                int e = tid + i * 256;               // float4 chunk id
                int r = e >> 5, c = e & 31;
                cpa16(qbs + (unsigned)(r*QSTRW + c*4)*4, Qg + (size_t)e*16);
            }
            const char* Kg = (const char*)(K + (size_t)j0 * 64 * DHEAD);
            const char* Vg = (const char*)(V + (size_t)j0 * 64 * DHEAD);
            #pragma unroll
            for (int i = 0; i < 8; i++) {
                int e = tid + i * 256;
                int r = e >> 5, c = e & 31;
                cpa16(kbs[0] + (unsigned)(r*KSTRW + c*4)*4, Kg + (size_t)e*16);
                cpa16(vbs[0] + (unsigned)(r*VSTRW + c*4)*4, Vg + (size_t)e*16);
            }
            CP_COMMIT;
            if (j0 + 1 < j1) {
                const char* Kg1 = (const char*)(K + (size_t)(j0+1) * 64 * DHEAD);
                const char* Vg1 = (const char*)(V + (size_t)(j0+1) * 64 * DHEAD);
                #pragma unroll
                for (int i = 0; i < 8; i++) {
                    int e = tid + i * 256;
                    int r = e >> 5, c = e & 31;
                    cpa16(kbs[1] + (unsigned)(r*KSTRW + c*4)*4, Kg1 + (size_t)e*16);
                    cpa16(vbs[1] + (unsigned)(r*VSTRW + c*4)*4, Vg1 + (size_t)e*16);
                }
            }
            CP_COMMIT;
        }

        float o[16][4] = {};
        float mA = -CUDART_INF_F, mB = -CUDART_INF_F;
        float lA = 0.f, lB = 0.f;

        for (int j = j0; j < j1; j++) {
            const int cur = (j - j0) & 1;
            CP_WAIT1;          // this tile's group complete (next may be pending)
            __syncthreads();   // all threads' copies visible

            const unsigned* Ksc = KsP[cur];
            const unsigned* Vsc = VsP[cur];

            // ---- S = Q @ K^T : per-warp 16x64 ----
            float s[8][4] = {};
            #pragma unroll
            for (int kt = 0; kt < 16; kt++) {
                unsigned a0 = Qs[(rA    )*QSTRW + kt*8 + t];
                unsigned a1 = Qs[(rA + 8)*QSTRW + kt*8 + t];
                unsigned a2 = Qs[(rA    )*QSTRW + kt*8 + t + 4];
                unsigned a3 = Qs[(rA + 8)*QSTRW + kt*8 + t + 4];
                #pragma unroll
                for (int nt = 0; nt < 8; nt++) {
                    unsigned b0 = Ksc[(nt*8 + g)*KSTRW + kt*8 + t];
                    unsigned b1 = Ksc[(nt*8 + g)*KSTRW + kt*8 + t + 4];
                    mma_tf32(s[nt], a0, a1, a2, a3, b0, b1);
                }
            }

            // ---- causal mask (diagonal band tiles only) ----
            if (j >= 2 * ib) {
                int rowA = qrow0 + rA, rowB = rowA + 8;
                #pragma unroll
                for (int nt = 0; nt < 8; nt++) {
                    int c0 = j*64 + nt*8 + 2*t;
                    if (c0     > rowA) s[nt][0] = -CUDART_INF_F;
                    if (c0 + 1 > rowA) s[nt][1] = -CUDART_INF_F;
                    if (c0     > rowB) s[nt][2] = -CUDART_INF_F;
                    if (c0 + 1 > rowB) s[nt][3] = -CUDART_INF_F;
                }
            }

            // ---- online softmax (P overwrites s, stays in registers) ----
            float tmA = -CUDART_INF_F, tmB = -CUDART_INF_F;
            #pragma unroll
            for (int nt = 0; nt < 8; nt++) {
                tmA = fmaxf(tmA, fmaxf(s[nt][0], s[nt][1]));
                tmB = fmaxf(tmB, fmaxf(s[nt][2], s[nt][3]));
            }
            tmA = fmaxf(tmA, __shfl_xor_sync(0xffffffffu, tmA, 1));
            tmA = fmaxf(tmA, __shfl_xor_sync(0xffffffffu, tmA, 2));
            tmB = fmaxf(tmB, __shfl_xor_sync(0xffffffffu, tmB, 1));
            tmB = fmaxf(tmB, __shfl_xor_sync(0xffffffffu, tmB, 2));

            float mnA = fmaxf(mA, tmA), mnB = fmaxf(mB, tmB);
            float scA = exp2f(mA - mnA), scB = exp2f(mB - mnB);
            mA = mnA; mB = mnB;

            float rsA = 0.f, rsB = 0.f;
            #pragma unroll
            for (int nt = 0; nt < 8; nt++) {
                float p0 = exp2f(s[nt][0] - mnA);
                float p1 = exp2f(s[nt][1] - mnA);
                float p2 = exp2f(s[nt][2] - mnB);
                float p3 = exp2f(s[nt][3] - mnB);
                rsA += p0 + p1;  rsB += p2 + p3;
                s[nt][0] = p0; s[nt][1] = p1; s[nt][2] = p2; s[nt][3] = p3;
            }
            lA = lA * scA + rsA;
            lB = lB * scB + rsB;

            #pragma unroll
            for (int nt = 0; nt < 16; nt++) {
                o[nt][0] *= scA; o[nt][1] *= scA;
                o[nt][2] *= scB; o[nt][3] *= scB;
            }

            // ---- O += P @ V : shuffle S-fragment -> A-fragment, K-dim 64 ----
            // S frag: slot0=(g,2t) slot1=(g,2t+1) slot2=(g+8,2t) slot3=(g+8,2t+1)
            // A frag needs: a0=(g,t) a1=(g+8,t) a2=(g,t+4) a3=(g+8,t+4)
            #pragma unroll
            for (int kt = 0; kt < 8; kt++) {
                int srcA = (lane & ~3) | (t >> 1);   // holds cols {t&~1, t|1}
                int srcB = srcA + 2;                 // holds cols {.. +4}
                float q0 = __shfl_sync(0xffffffffu, s[kt][0], srcA);
                float q1 = __shfl_sync(0xffffffffu, s[kt][1], srcA);
                float q2 = __shfl_sync(0xffffffffu, s[kt][2], srcA);
                float q3 = __shfl_sync(0xffffffffu, s[kt][3], srcA);
                float r0 = __shfl_sync(0xffffffffu, s[kt][0], srcB);
                float r1 = __shfl_sync(0xffffffffu, s[kt][1], srcB);
                float r2 = __shfl_sync(0xffffffffu, s[kt][2], srcB);
                float r3 = __shfl_sync(0xffffffffu, s[kt][3], srcB);
                bool odd = (t & 1);
                unsigned a0 = f2tf32(odd ? q1 : q0);   // (g,    t)
                unsigned a1 = f2tf32(odd ? q3 : q2);   // (g+8,  t)
                unsigned a2 = f2tf32(odd ? r1 : r0);   // (g,    t+4)
                unsigned a3 = f2tf32(odd ? r3 : r2);   // (g+8,  t+4)
                #pragma unroll
                for (int nt = 0; nt < 16; nt++) {
                    unsigned b0 = Vsc[(kt*8 + t    )*VSTRW + nt*8 + g];
                    unsigned b1 = Vsc[(kt*8 + t + 4)*VSTRW + nt*8 + g];
                    mma_tf32(o[nt], a0, a1, a2, a3, b0, b1);
                }
            }

            __syncthreads();   // all warps done reading buf cur
            if (j + 2 < j1) {  // prefetch j+2 into the buffer just freed
                const char* Kg = (const char*)(K + (size_t)(j+2) * 64 * DHEAD);
                const char* Vg = (const char*)(V + (size_t)(j+2) * 64 * DHEAD);
                #pragma unroll
                for (int i = 0; i < 8; i++) {
                    int e = tid + i * 256;
                    int r = e >> 5, c = e & 31;
                    cpa16(kbs[cur] + (unsigned)(r*KSTRW + c*4)*4, Kg + (size_t)e*16);
                    cpa16(vbs[cur] + (unsigned)(r*VSTRW + c*4)*4, Vg + (size_t)e*16);
                }
            }
            CP_COMMIT;         // always commit (possibly empty) to keep counts aligned
        }

        // ---- write un-normalized partial (O, m, l) ----
        lA += __shfl_xor_sync(0xffffffffu, lA, 1);
        lA += __shfl_xor_sync(0xffffffffu, lA, 2);
        lB += __shfl_xor_sync(0xffffffffu, lB, 1);
        lB += __shfl_xor_sync(0xffffffffu, lB, 2);

        float* PO = g_pO + (size_t)slot * 128 * DHEAD;
        #pragma unroll
        for (int nt = 0; nt < 16; nt++) {
            int c = nt*8 + 2*t;
            float2 v0 = make_float2(o[nt][0], o[nt][1]);
            float2 v1 = make_float2(o[nt][2], o[nt][3]);
            *(float2*)&PO[(size_t)rA * DHEAD + c]       = v0;
            *(float2*)&PO[(size_t)(rA + 8) * DHEAD + c] = v1;
        }
        if (t == 0) {
            g_pm[slot*128 + rA]     = mA;
            g_pm[slot*128 + rA + 8] = mB;
            g_pl[slot*128 + rA]     = lA;
            g_pl[slot*128 + rA + 8] = lB;
        }
    }
}

// ============================================================================
// Combine partials: out = (sum_c 2^(m_c-Mg) O_c) / (sum_c 2^(m_c-Mg) l_c)
// One CTA per (batch, qblock). Also resets the work counter for next replay.
// ============================================================================
__global__ __launch_bounds__(256) void combine_kernel(float* __restrict__ out)
{
    if (blockIdx.x == 0 && threadIdx.x == 0) g_ctr = 0;  // flash already done

    const int b  = blockIdx.x >> 5;
    const int ib = blockIdx.x & 31;
    const int jmax = 2*ib + 2;
    const int n    = (jmax + CHUNK - 1) / CHUNK;
    const int base = (b*32 + ib) << 2;
    const int tid  = threadIdx.x;

    __shared__ float w[4][128];
    __shared__ float invL[128];

    if (tid < 128) {
        float mv[4];
        float Mg = -CUDART_INF_F;
        for (int c = 0; c < n; c++) {
            mv[c] = g_pm[(base + c)*128 + tid];
            Mg = fmaxf(Mg, mv[c]);
        }
        float L = 0.f;
        for (int c = 0; c < n; c++) {
            float wc = exp2f(mv[c] - Mg);
            w[c][tid] = wc;
            L += wc * g_pl[(base + c)*128 + tid];
        }
        invL[tid] = 1.f / L;
    }
    __syncthreads();

    float* O = out + ((size_t)b * SEQ + ib * 128) * DHEAD;
    for (int e = tid; e < 128 * 32; e += 256) {     // float4 granularity
        int r  = e >> 5;
        int c4 = (e & 31) * 4;
        float4 acc = make_float4(0.f, 0.f, 0.f, 0.f);
        for (int c = 0; c < n; c++) {
            const float4 p = *(const float4*)&g_pO[((size_t)(base + c) * 128 + r) * DHEAD + c4];
            float wc = w[c][r];
            acc.x += wc * p.x; acc.y += wc * p.y;
            acc.z += wc * p.z; acc.w += wc * p.w;
        }
        float il = invL[r];
        acc.x *= il; acc.y *= il; acc.z *= il; acc.w *= il;
        *(float4*)&O[(size_t)r * DHEAD + c4] = acc;
    }
}

// ============================================================================
extern "C" void kernel_launch(void* const* d_in, const int* in_sizes, int n_in,
                              void* d_out, int out_size)
{
    const float* q  = (const float*)d_in[0];
    const float* k  = (const float*)d_in[1];
    const float* v  = (const float*)d_in[2];
    const float* wq = (const float*)d_in[3];
    const float* wk = (const float*)d_in[4];
    const float* wv = (const float*)d_in[5];
    float* out = (float*)d_out;

    cudaFuncSetAttribute(flash_kernel,
                         cudaFuncAttributeMaxDynamicSharedMemorySize, FLASH_SMEM);

    proj_kernel<<<dim3(MROWS/128, 1, 3), 256>>>(q, k, v, wq, wk, wv);
    flash_kernel<<<148, 256, FLASH_SMEM>>>();
    combine_kernel<<<BATCH*32, 256>>>(out);
}

// round 13
// speedup vs baseline: 1.3526x; 1.3526x over previous
#include <cuda_runtime.h>
#include <cuda_fp16.h>
#include <math_constants.h>
#include <cstdint>

#define BATCH 4
#define SEQ 4096
#define DMODEL 1024
#define DHEAD 128
#define MROWS (BATCH*SEQ)   // 16384

#define CHUNK 16            // max KV tiles (of 64 keys) per work unit
#define NUNITS 320          // 4 batches * sum_ib ceil((2ib+2)/16) = 4*80
#define NSLOTS 512          // (b*32+ib)*4 + c, c < 4

#define QSCALEF (1.4426950408889634f * 0.08838834764831845f)  // log2e/sqrt(128)

// Scratch (device globals: no allocations allowed).
// Projected Q/K/V stored as fp16 (Q pre-scaled by QSCALEF in proj epilogue).
__device__ __align__(16) __half g_Qh[MROWS*DHEAD];
__device__ __align__(16) __half g_Kh[MROWS*DHEAD];
__device__ __align__(16) __half g_Vh[MROWS*DHEAD];
__device__ float g_pO[NSLOTS*128*DHEAD];   // un-normalized partial O per slot
__device__ float g_pm[NSLOTS*128];         // per-row running max (exp2 domain)
__device__ float g_pl[NSLOTS*128];         // per-row partial denom
__device__ int   g_ctr;                    // persistent-kernel work counter

__device__ __forceinline__ unsigned f2tf32(float x){
    unsigned y; asm("cvt.rna.tf32.f32 %0, %1;" : "=r"(y) : "f"(x)); return y;
}

// tf32 HMMA (projections)
__device__ __forceinline__ void mma_tf32(float* d,
    unsigned a0, unsigned a1, unsigned a2, unsigned a3,
    unsigned b0, unsigned b1)
{
    asm volatile(
        "mma.sync.aligned.m16n8k8.row.col.f32.tf32.tf32.f32 "
        "{%0,%1,%2,%3}, {%4,%5,%6,%7}, {%8,%9}, {%0,%1,%2,%3};"
        : "+f"(d[0]), "+f"(d[1]), "+f"(d[2]), "+f"(d[3])
        : "r"(a0), "r"(a1), "r"(a2), "r"(a3), "r"(b0), "r"(b1));
}

// fp16 HMMA, f32 accumulate (attention) — C layout identical to m16n8k8
__device__ __forceinline__ void mma_f16(float* d,
    unsigned a0, unsigned a1, unsigned a2, unsigned a3,
    unsigned b0, unsigned b1)
{
    asm volatile(
        "mma.sync.aligned.m16n8k16.row.col.f32.f16.f16.f32 "
        "{%0,%1,%2,%3}, {%4,%5,%6,%7}, {%8,%9}, {%0,%1,%2,%3};"
        : "+f"(d[0]), "+f"(d[1]), "+f"(d[2]), "+f"(d[3])
        : "r"(a0), "r"(a1), "r"(a2), "r"(a3), "r"(b0), "r"(b1));
}

// ============================================================================
// Projection: Y[16384,128] = X[16384,1024] @ W[128,1024]^T   (tf32 HMMA)
// Same structure as the measured-153us kernel; epilogue stores fp16
// (Q pre-scaled by QSCALEF).
// ============================================================================
#define PSTR 36

__global__ __launch_bounds__(256, 2) void proj_kernel(
    const float* __restrict__ q, const float* __restrict__ k, const float* __restrict__ v,
    const float* __restrict__ wq, const float* __restrict__ wk, const float* __restrict__ wv)
{
    __shared__ unsigned Xs[128*PSTR];
    __shared__ unsigned Ws[128*PSTR];

    const float* X; const float* W; __half* Y;
    if (blockIdx.z == 0)      { X = q; W = wq; Y = g_Qh; }
    else if (blockIdx.z == 1) { X = k; W = wk; Y = g_Kh; }
    else                      { X = v; W = wv; Y = g_Vh; }

    const int row0 = blockIdx.x * 128;
    const int tid  = threadIdx.x;
    const int wid  = tid >> 5;
    const int lane = tid & 31;
    const int g    = lane >> 2;
    const int t    = lane & 3;
    const int wr   = (wid >> 1) * 32;
    const int wc   = (wid & 1) * 64;

    float acc[2][8][4] = {};

    for (int k0 = 0; k0 < DMODEL; k0 += 32) {
        #pragma unroll
        for (int i = 0; i < 4; i++) {
            int e = tid + i * 256;
            int r = e >> 3, c = e & 7;
            float4 x = *(const float4*)&X[(size_t)(row0 + r) * DMODEL + k0 + c*4];
            float4 w = *(const float4*)&W[(size_t)r * DMODEL + k0 + c*4];
            uint4 xt = { f2tf32(x.x), f2tf32(x.y), f2tf32(x.z), f2tf32(x.w) };
            uint4 wt = { f2tf32(w.x), f2tf32(w.y), f2tf32(w.z), f2tf32(w.w) };
            *(uint4*)&Xs[r*PSTR + c*4] = xt;
            *(uint4*)&Ws[r*PSTR + c*4] = wt;
        }
        __syncthreads();

        #pragma unroll
        for (int kt = 0; kt < 4; kt++) {
            unsigned a[2][4];
            #pragma unroll
            for (int mt = 0; mt < 2; mt++) {
                int r = wr + mt * 16;
                a[mt][0] = Xs[(r + g    )*PSTR + kt*8 + t];
                a[mt][1] = Xs[(r + g + 8)*PSTR + kt*8 + t];
                a[mt][2] = Xs[(r + g    )*PSTR + kt*8 + t + 4];
                a[mt][3] = Xs[(r + g + 8)*PSTR + kt*8 + t + 4];
            }
            #pragma unroll
            for (int nt = 0; nt < 8; nt++) {
                unsigned b0 = Ws[(wc + nt*8 + g)*PSTR + kt*8 + t];
                unsigned b1 = Ws[(wc + nt*8 + g)*PSTR + kt*8 + t + 4];
                mma_tf32(acc[0][nt], a[0][0], a[0][1], a[0][2], a[0][3], b0, b1);
                mma_tf32(acc[1][nt], a[1][0], a[1][1], a[1][2], a[1][3], b0, b1);
            }
        }
        __syncthreads();
    }

    const float scale = (blockIdx.z == 0) ? QSCALEF : 1.0f;
    #pragma unroll
    for (int mt = 0; mt < 2; mt++) {
        int r = row0 + wr + mt*16 + g;
        #pragma unroll
        for (int nt = 0; nt < 8; nt++) {
            int c = wc + nt*8 + 2*t;
            __half2 v0 = __floats2half2_rn(acc[mt][nt][0]*scale, acc[mt][nt][1]*scale);
            __half2 v1 = __floats2half2_rn(acc[mt][nt][2]*scale, acc[mt][nt][3]*scale);
            *(__half2*)&Y[(size_t)r * DHEAD + c]       = v0;
            *(__half2*)&Y[(size_t)(r + 8) * DHEAD + c] = v1;
        }
    }
}

// ============================================================================
// Split-KV flash attention, causal, fp16 MMA (m16n8k16). R6 structure:
// persistent CTAs + LPT units, synchronous staging between two barriers,
// P routed through smem. Smem layouts (4B words):
//   Qs: 128 x 68   word (r,c) = halfs (2c,2c+1) of Q row r
//   Ks: 64  x 68   same layout for K
//   Vp: 32  x 132  word (p,n) = half2( V[2p][n], V[2p+1][n] )  (key pairs)
//   Ps: 128 x 36   word (r,c) = half2( P[r][2c], P[r][2c+1] )
// ============================================================================
#define QSH 68
#define KSH 68
#define VPSH 132
#define PSH 36
#define QWsz (128*QSH)    // 8704 words
#define KWsz (64*KSH)     // 4352
#define VWsz (32*VPSH)    // 4224
#define PWsz (128*PSH)    // 4608
#define FLASH_SMEM ((QWsz + KWsz + VWsz + PWsz) * 4)   // 87552 B

__device__ __forceinline__ void decode_unit(int u, int& b, int& ib,
                                            int& j0, int& j1, int& slot)
{
    b = u & 3;
    int v = u >> 2;              // 0..79, descending-ib order (big units first)
    int acc = 0, ibb = 0, n = 1;
    #pragma unroll 1
    for (int i = 31; i >= 0; --i) {
        int jm = 2*i + 2;
        int ni = (jm + CHUNK - 1) / CHUNK;
        if (v < acc + ni) { ibb = i; n = ni; break; }
        acc += ni;
    }
    int c    = v - acc;
    int jmax = 2*ibb + 2;
    int len  = (jmax + n - 1) / n;
    j0 = c * len;
    j1 = min(jmax, j0 + len);
    ib = ibb;
    slot = ((b*32 + ibb) << 2) + c;
}

__global__ __launch_bounds__(256, 1) void flash_kernel()
{
    extern __shared__ unsigned sm[];
    unsigned* Qs = sm;
    unsigned* Ks = Qs + QWsz;
    unsigned* Vp = Ks + KWsz;
    unsigned* Ps = Vp + VWsz;
    __shared__ int s_unit;

    const int tid  = threadIdx.x;
    const int wid  = tid >> 5;
    const int lane = tid & 31;
    const int g    = lane >> 2;
    const int t    = lane & 3;
    const int rA   = wid * 16 + g;   // local row (and rA+8)

    for (;;) {
        if (tid == 0) s_unit = atomicAdd(&g_ctr, 1);
        __syncthreads();             // broadcast; also fences prior unit's smem reads
        int u = s_unit;
        if (u >= NUNITS) break;

        int b, ib, j0, j1, slot;
        decode_unit(u, b, ib, j0, j1, slot);
        const int qrow0 = ib * 128;
        const __half* Qg = g_Qh + (size_t)b * SEQ * DHEAD;
        const __half* Kg = g_Kh + (size_t)b * SEQ * DHEAD;
        const __half* Vg = g_Vh + (size_t)b * SEQ * DHEAD;

        // ---- stage Q tile: 128x128 fp16, 2048 uint4, coalesced ----
        {
            const uint4* Q4 = (const uint4*)(Qg + (size_t)qrow0 * DHEAD);
            #pragma unroll
            for (int i = 0; i < 8; i++) {
                int e = tid + i * 256;
                int r = e >> 4, c = e & 15;
                *(uint4*)&Qs[r*QSH + 4*c] = Q4[e];
            }
        }

        float o[16][4] = {};
        float mA = -CUDART_INF_F, mB = -CUDART_INF_F;
        float lA = 0.f, lB = 0.f;

        for (int j = j0; j < j1; j++) {
            __syncthreads();   // prev tile's reads done (also orders Q staging)
            {
                // K tile: 64x128 fp16, 1024 uint4
                const uint4* K4 = (const uint4*)(Kg + (size_t)j * 64 * DHEAD);
                #pragma unroll
                for (int i = 0; i < 4; i++) {
                    int e = tid + i * 256;
                    int r = e >> 4, c = e & 15;
                    *(uint4*)&Ks[r*KSH + 4*c] = K4[e];
                }
                // V tile: pair-interleave keys (2p,2p+1) -> Vp[p][dim]
                const uint4* V4 = (const uint4*)(Vg + (size_t)j * 64 * DHEAD);
                #pragma unroll
                for (int i = 0; i < 2; i++) {
                    int e = tid + i * 256;          // pair-unit id, 0..511
                    int p = e >> 4, c = e & 15;     // pair row, uint4 col (8 dims)
                    uint4 lo = V4[(2*p    )*16 + c];
                    uint4 hi = V4[(2*p + 1)*16 + c];
                    uint4 w0, w1;
                    w0.x = __byte_perm(lo.x, hi.x, 0x5410);
                    w0.y = __byte_perm(lo.x, hi.x, 0x7632);
                    w0.z = __byte_perm(lo.y, hi.y, 0x5410);
                    w0.w = __byte_perm(lo.y, hi.y, 0x7632);
                    w1.x = __byte_perm(lo.z, hi.z, 0x5410);
                    w1.y = __byte_perm(lo.z, hi.z, 0x7632);
                    w1.z = __byte_perm(lo.w, hi.w, 0x5410);
                    w1.w = __byte_perm(lo.w, hi.w, 0x7632);
                    *(uint4*)&Vp[p*VPSH + 8*c]     = w0;
                    *(uint4*)&Vp[p*VPSH + 8*c + 4] = w1;
                }
            }
            __syncthreads();

            // ---- S = Q @ K^T : per-warp 16x64, fp16 k16 ----
            float s[8][4] = {};
            #pragma unroll
            for (int kt = 0; kt < 8; kt++) {
                unsigned a0 = Qs[(rA    )*QSH + kt*8 + t];
                unsigned a1 = Qs[(rA + 8)*QSH + kt*8 + t];
                unsigned a2 = Qs[(rA    )*QSH + kt*8 + t + 4];
                unsigned a3 = Qs[(rA + 8)*QSH + kt*8 + t + 4];
                #pragma unroll
                for (int nt = 0; nt < 8; nt++) {
                    unsigned b0 = Ks[(nt*8 + g)*KSH + kt*8 + t];
                    unsigned b1 = Ks[(nt*8 + g)*KSH + kt*8 + t + 4];
                    mma_f16(s[nt], a0, a1, a2, a3, b0, b1);
                }
            }

            // ---- causal mask (diagonal band tiles only) ----
            if (j >= 2 * ib) {
                int rowA = qrow0 + rA, rowB = rowA + 8;
                #pragma unroll
                for (int nt = 0; nt < 8; nt++) {
                    int c0 = j*64 + nt*8 + 2*t;
                    if (c0     > rowA) s[nt][0] = -CUDART_INF_F;
                    if (c0 + 1 > rowA) s[nt][1] = -CUDART_INF_F;
                    if (c0     > rowB) s[nt][2] = -CUDART_INF_F;
                    if (c0 + 1 > rowB) s[nt][3] = -CUDART_INF_F;
                }
            }

            // ---- online softmax ----
            float tmA = -CUDART_INF_F, tmB = -CUDART_INF_F;
            #pragma unroll
            for (int nt = 0; nt < 8; nt++) {
                tmA = fmaxf(tmA, fmaxf(s[nt][0], s[nt][1]));
                tmB = fmaxf(tmB, fmaxf(s[nt][2], s[nt][3]));
            }
            tmA = fmaxf(tmA, __shfl_xor_sync(0xffffffffu, tmA, 1));
            tmA = fmaxf(tmA, __shfl_xor_sync(0xffffffffu, tmA, 2));
            tmB = fmaxf(tmB, __shfl_xor_sync(0xffffffffu, tmB, 1));
            tmB = fmaxf(tmB, __shfl_xor_sync(0xffffffffu, tmB, 2));

            float mnA = fmaxf(mA, tmA), mnB = fmaxf(mB, tmB);
            float scA = exp2f(mA - mnA), scB = exp2f(mB - mnB);
            mA = mnA; mB = mnB;

            float rsA = 0.f, rsB = 0.f;
            #pragma unroll
            for (int nt = 0; nt < 8; nt++) {
                float p0 = exp2f(s[nt][0] - mnA);
                float p1 = exp2f(s[nt][1] - mnA);
                float p2 = exp2f(s[nt][2] - mnB);
                float p3 = exp2f(s[nt][3] - mnB);
                rsA += p0 + p1;  rsB += p2 + p3;
                __half2 hA = __floats2half2_rn(p0, p1);   // lo = col 2t
                __half2 hB = __floats2half2_rn(p2, p3);
                Ps[(rA    )*PSH + nt*4 + t] = *(unsigned*)&hA;
                Ps[(rA + 8)*PSH + nt*4 + t] = *(unsigned*)&hB;
            }
            lA = lA * scA + rsA;
            lB = lB * scB + rsB;

            #pragma unroll
            for (int nt = 0; nt < 16; nt++) {
                o[nt][0] *= scA; o[nt][1] *= scA;
                o[nt][2] *= scB; o[nt][3] *= scB;
            }

            __syncwarp();  // P tile is warp-private: writes before fragment reads

            // ---- O += P @ V : per-warp 16x128, fp16 k16 (4 kt over 64 keys) ----
            #pragma unroll
            for (int kt = 0; kt < 4; kt++) {
                unsigned a0 = Ps[(rA    )*PSH + kt*8 + t];
                unsigned a1 = Ps[(rA + 8)*PSH + kt*8 + t];
                unsigned a2 = Ps[(rA    )*PSH + kt*8 + t + 4];
                unsigned a3 = Ps[(rA + 8)*PSH + kt*8 + t + 4];
                #pragma unroll
                for (int nt = 0; nt < 16; nt++) {
                    unsigned b0 = Vp[(kt*8 + t    )*VPSH + nt*8 + g];
                    unsigned b1 = Vp[(kt*8 + t + 4)*VPSH + nt*8 + g];
                    mma_f16(o[nt], a0, a1, a2, a3, b0, b1);
                }
            }
        }

        // ---- write un-normalized partial (O, m, l) ----
        lA += __shfl_xor_sync(0xffffffffu, lA, 1);
        lA += __shfl_xor_sync(0xffffffffu, lA, 2);
        lB += __shfl_xor_sync(0xffffffffu, lB, 1);
        lB += __shfl_xor_sync(0xffffffffu, lB, 2);

        float* PO = g_pO + (size_t)slot * 128 * DHEAD;
        #pragma unroll
        for (int nt = 0; nt < 16; nt++) {
            int c = nt*8 + 2*t;
            float2 v0 = make_float2(o[nt][0], o[nt][1]);
            float2 v1 = make_float2(o[nt][2], o[nt][3]);
            *(float2*)&PO[(size_t)rA * DHEAD + c]       = v0;
            *(float2*)&PO[(size_t)(rA + 8) * DHEAD + c] = v1;
        }
        if (t == 0) {
            g_pm[slot*128 + rA]     = mA;
            g_pm[slot*128 + rA + 8] = mB;
            g_pl[slot*128 + rA]     = lA;
            g_pl[slot*128 + rA + 8] = lB;
        }
    }
}

// ============================================================================
// Combine partials: out = (sum_c 2^(m_c-Mg) O_c) / (sum_c 2^(m_c-Mg) l_c)
// One CTA per (batch, qblock). Also resets the work counter for next replay.
// ============================================================================
__global__ __launch_bounds__(256) void combine_kernel(float* __restrict__ out)
{
    if (blockIdx.x == 0 && threadIdx.x == 0) g_ctr = 0;  // flash already done

    const int b  = blockIdx.x >> 5;
    const int ib = blockIdx.x & 31;
    const int jmax = 2*ib + 2;
    const int n    = (jmax + CHUNK - 1) / CHUNK;
    const int base = (b*32 + ib) << 2;
    const int tid  = threadIdx.x;

    __shared__ float w[4][128];
    __shared__ float invL[128];

    if (tid < 128) {
        float mv[4];
        float Mg = -CUDART_INF_F;
        for (int c = 0; c < n; c++) {
            mv[c] = g_pm[(base + c)*128 + tid];
            Mg = fmaxf(Mg, mv[c]);
        }
        float L = 0.f;
        for (int c = 0; c < n; c++) {
            float wc = exp2f(mv[c] - Mg);
            w[c][tid] = wc;
            L += wc * g_pl[(base + c)*128 + tid];
        }
        invL[tid] = 1.f / L;
    }
    __syncthreads();

    float* O = out + ((size_t)b * SEQ + ib * 128) * DHEAD;
    for (int e = tid; e < 128 * 32; e += 256) {     // float4 granularity
        int r  = e >> 5;
        int c4 = (e & 31) * 4;
        float4 acc = make_float4(0.f, 0.f, 0.f, 0.f);
        for (int c = 0; c < n; c++) {
            const float4 p = *(const float4*)&g_pO[((size_t)(base + c) * 128 + r) * DHEAD + c4];
            float wc = w[c][r];
            acc.x += wc * p.x; acc.y += wc * p.y;
            acc.z += wc * p.z; acc.w += wc * p.w;
        }
        float il = invL[r];
        acc.x *= il; acc.y *= il; acc.z *= il; acc.w *= il;
        *(float4*)&O[(size_t)r * DHEAD + c4] = acc;
    }
}

// ============================================================================
extern "C" void kernel_launch(void* const* d_in, const int* in_sizes, int n_in,
                              void* d_out, int out_size)
{
    const float* q  = (const float*)d_in[0];
    const float* k  = (const float*)d_in[1];
    const float* v  = (const float*)d_in[2];
    const float* wq = (const float*)d_in[3];
    const float* wk = (const float*)d_in[4];
    const float* wv = (const float*)d_in[5];
    float* out = (float*)d_out;

    cudaFuncSetAttribute(flash_kernel,
                         cudaFuncAttributeMaxDynamicSharedMemorySize, FLASH_SMEM);

    proj_kernel<<<dim3(MROWS/128, 1, 3), 256>>>(q, k, v, wq, wk, wv);
    flash_kernel<<<148, 256, FLASH_SMEM>>>();
    combine_kernel<<<BATCH*32, 256>>>(out);
}

// round 14
// speedup vs baseline: 1.5925x; 1.1774x over previous
#include <cuda_runtime.h>
#include <cuda_fp16.h>
#include <math_constants.h>
#include <cstdint>

#define BATCH 4
#define SEQ 4096
#define DMODEL 1024
#define DHEAD 128
#define MROWS (BATCH*SEQ)   // 16384

#define CHUNK 16            // max KV tiles (of 64 keys) per work unit
#define NUNITS 320          // 4 batches * sum_ib ceil((2ib+2)/16) = 4*80
#define NSLOTS 512          // (b*32+ib)*4 + c, c < 4

#define QSCALEF (1.4426950408889634f * 0.08838834764831845f)  // log2e/sqrt(128)

// Scratch (device globals: no allocations allowed).
// Projected Q/K/V stored as fp16 (Q pre-scaled by QSCALEF in proj epilogue).
__device__ __align__(16) __half g_Qh[MROWS*DHEAD];
__device__ __align__(16) __half g_Kh[MROWS*DHEAD];
__device__ __align__(16) __half g_Vh[MROWS*DHEAD];
__device__ float g_pO[NSLOTS*128*DHEAD];   // un-normalized partial O per slot
__device__ float g_pm[NSLOTS*128];         // per-row running max (exp2 domain)
__device__ float g_pl[NSLOTS*128];         // per-row partial denom
__device__ int   g_ctr;                    // persistent-kernel work counter

// fp16 HMMA, f32 accumulate — C layout identical to m16n8k8
__device__ __forceinline__ void mma_f16(float* d,
    unsigned a0, unsigned a1, unsigned a2, unsigned a3,
    unsigned b0, unsigned b1)
{
    asm volatile(
        "mma.sync.aligned.m16n8k16.row.col.f32.f16.f16.f32 "
        "{%0,%1,%2,%3}, {%4,%5,%6,%7}, {%8,%9}, {%0,%1,%2,%3};"
        : "+f"(d[0]), "+f"(d[1]), "+f"(d[2]), "+f"(d[3])
        : "r"(a0), "r"(a1), "r"(a2), "r"(a3), "r"(b0), "r"(b1));
}

__device__ __forceinline__ unsigned h2bits(float a, float b){
    __half2 h = __floats2half2_rn(a, b);
    return *(unsigned*)&h;
}

// ============================================================================
// Projection: Y[16384,128] = X[16384,1024] @ W[128,1024]^T   (fp16 HMMA k16)
// CTA tile 128x128, K-step 64. 8 warps in 4x2 grid, each warp 32x64.
// Smem word (r,c) = halfs (2c,2c+1) of row r; stride 36 words (conflict-free:
// fragment address (4g+t) mod 32 covers 0..31).
// ============================================================================
#define PJSH 36

__global__ __launch_bounds__(256, 2) void proj_kernel(
    const float* __restrict__ q, const float* __restrict__ k, const float* __restrict__ v,
    const float* __restrict__ wq, const float* __restrict__ wk, const float* __restrict__ wv)
{
    __shared__ unsigned Xs[128*PJSH];
    __shared__ unsigned Ws[128*PJSH];

    const float* X; const float* W; __half* Y;
    if (blockIdx.z == 0)      { X = q; W = wq; Y = g_Qh; }
    else if (blockIdx.z == 1) { X = k; W = wk; Y = g_Kh; }
    else                      { X = v; W = wv; Y = g_Vh; }

    const int row0 = blockIdx.x * 128;
    const int tid  = threadIdx.x;
    const int wid  = tid >> 5;
    const int lane = tid & 31;
    const int g    = lane >> 2;
    const int t    = lane & 3;
    const int wr   = (wid >> 1) * 32;
    const int wc   = (wid & 1) * 64;

    float acc[2][8][4] = {};

    for (int k0 = 0; k0 < DMODEL; k0 += 64) {
        // stage 128x64 fp32 -> fp16: 8 float4 each of X and W per thread
        #pragma unroll
        for (int i = 0; i < 8; i++) {
            int e = tid + i * 256;         // float4 id, 0..2047
            int r = e >> 4, c = e & 15;    // row, float4-col (16 per 64-wide row)
            float4 x = *(const float4*)&X[(size_t)(row0 + r) * DMODEL + k0 + c*4];
            float4 w = *(const float4*)&W[(size_t)r * DMODEL + k0 + c*4];
            uint2 xw = { h2bits(x.x, x.y), h2bits(x.z, x.w) };
            uint2 ww = { h2bits(w.x, w.y), h2bits(w.z, w.w) };
            *(uint2*)&Xs[r*PJSH + c*2] = xw;
            *(uint2*)&Ws[r*PJSH + c*2] = ww;
        }
        __syncthreads();

        #pragma unroll
        for (int kt = 0; kt < 4; kt++) {      // 4 x k16 = 64
            unsigned a[2][4];
            #pragma unroll
            for (int mt = 0; mt < 2; mt++) {
                int r = wr + mt * 16;
                a[mt][0] = Xs[(r + g    )*PJSH + kt*8 + t];
                a[mt][1] = Xs[(r + g + 8)*PJSH + kt*8 + t];
                a[mt][2] = Xs[(r + g    )*PJSH + kt*8 + t + 4];
                a[mt][3] = Xs[(r + g + 8)*PJSH + kt*8 + t + 4];
            }
            #pragma unroll
            for (int nt = 0; nt < 8; nt++) {
                unsigned b0 = Ws[(wc + nt*8 + g)*PJSH + kt*8 + t];
                unsigned b1 = Ws[(wc + nt*8 + g)*PJSH + kt*8 + t + 4];
                mma_f16(acc[0][nt], a[0][0], a[0][1], a[0][2], a[0][3], b0, b1);
                mma_f16(acc[1][nt], a[1][0], a[1][1], a[1][2], a[1][3], b0, b1);
            }
        }
        __syncthreads();
    }

    const float scale = (blockIdx.z == 0) ? QSCALEF : 1.0f;
    #pragma unroll
    for (int mt = 0; mt < 2; mt++) {
        int r = row0 + wr + mt*16 + g;
        #pragma unroll
        for (int nt = 0; nt < 8; nt++) {
            int c = wc + nt*8 + 2*t;
            __half2 v0 = __floats2half2_rn(acc[mt][nt][0]*scale, acc[mt][nt][1]*scale);
            __half2 v1 = __floats2half2_rn(acc[mt][nt][2]*scale, acc[mt][nt][3]*scale);
            *(__half2*)&Y[(size_t)r * DHEAD + c]       = v0;
            *(__half2*)&Y[(size_t)(r + 8) * DHEAD + c] = v1;
        }
    }
}

// ============================================================================
// Split-KV flash attention, causal, fp16 MMA (m16n8k16).  [unchanged from R13]
// Smem layouts (4B words):
//   Qs: 128 x 68   word (r,c) = halfs (2c,2c+1) of Q row r
//   Ks: 64  x 68   same layout for K
//   Vp: 32  x 132  word (p,n) = half2( V[2p][n], V[2p+1][n] )  (key pairs)
//   Ps: 128 x 36   word (r,c) = half2( P[r][2c], P[r][2c+1] )
// ============================================================================
#define QSH 68
#define KSH 68
#define VPSH 132
#define PSH 36
#define QWsz (128*QSH)    // 8704 words
#define KWsz (64*KSH)     // 4352
#define VWsz (32*VPSH)    // 4224
#define PWsz (128*PSH)    // 4608
#define FLASH_SMEM ((QWsz + KWsz + VWsz + PWsz) * 4)   // 87552 B

__device__ __forceinline__ void decode_unit(int u, int& b, int& ib,
                                            int& j0, int& j1, int& slot)
{
    b = u & 3;
    int v = u >> 2;              // 0..79, descending-ib order (big units first)
    int acc = 0, ibb = 0, n = 1;
    #pragma unroll 1
    for (int i = 31; i >= 0; --i) {
        int jm = 2*i + 2;
        int ni = (jm + CHUNK - 1) / CHUNK;
        if (v < acc + ni) { ibb = i; n = ni; break; }
        acc += ni;
    }
    int c    = v - acc;
    int jmax = 2*ibb + 2;
    int len  = (jmax + n - 1) / n;
    j0 = c * len;
    j1 = min(jmax, j0 + len);
    ib = ibb;
    slot = ((b*32 + ibb) << 2) + c;
}

__global__ __launch_bounds__(256, 1) void flash_kernel()
{
    extern __shared__ unsigned sm[];
    unsigned* Qs = sm;
    unsigned* Ks = Qs + QWsz;
    unsigned* Vp = Ks + KWsz;
    unsigned* Ps = Vp + VWsz;
    __shared__ int s_unit;

    const int tid  = threadIdx.x;
    const int wid  = tid >> 5;
    const int lane = tid & 31;
    const int g    = lane >> 2;
    const int t    = lane & 3;
    const int rA   = wid * 16 + g;   // local row (and rA+8)

    for (;;) {
        if (tid == 0) s_unit = atomicAdd(&g_ctr, 1);
        __syncthreads();             // broadcast; also fences prior unit's smem reads
        int u = s_unit;
        if (u >= NUNITS) break;

        int b, ib, j0, j1, slot;
        decode_unit(u, b, ib, j0, j1, slot);
        const int qrow0 = ib * 128;
        const __half* Qg = g_Qh + (size_t)b * SEQ * DHEAD;
        const __half* Kg = g_Kh + (size_t)b * SEQ * DHEAD;
        const __half* Vg = g_Vh + (size_t)b * SEQ * DHEAD;

        // ---- stage Q tile: 128x128 fp16, 2048 uint4, coalesced ----
        {
            const uint4* Q4 = (const uint4*)(Qg + (size_t)qrow0 * DHEAD);
            #pragma unroll
            for (int i = 0; i < 8; i++) {
                int e = tid + i * 256;
                int r = e >> 4, c = e & 15;
                *(uint4*)&Qs[r*QSH + 4*c] = Q4[e];
            }
        }

        float o[16][4] = {};
        float mA = -CUDART_INF_F, mB = -CUDART_INF_F;
        float lA = 0.f, lB = 0.f;

        for (int j = j0; j < j1; j++) {
            __syncthreads();   // prev tile's reads done (also orders Q staging)
            {
                // K tile: 64x128 fp16, 1024 uint4
                const uint4* K4 = (const uint4*)(Kg + (size_t)j * 64 * DHEAD);
                #pragma unroll
                for (int i = 0; i < 4; i++) {
                    int e = tid + i * 256;
                    int r = e >> 4, c = e & 15;
                    *(uint4*)&Ks[r*KSH + 4*c] = K4[e];
                }
                // V tile: pair-interleave keys (2p,2p+1) -> Vp[p][dim]
                const uint4* V4 = (const uint4*)(Vg + (size_t)j * 64 * DHEAD);
                #pragma unroll
                for (int i = 0; i < 2; i++) {
                    int e = tid + i * 256;          // pair-unit id, 0..511
                    int p = e >> 4, c = e & 15;     // pair row, uint4 col (8 dims)
                    uint4 lo = V4[(2*p    )*16 + c];
                    uint4 hi = V4[(2*p + 1)*16 + c];
                    uint4 w0, w1;
                    w0.x = __byte_perm(lo.x, hi.x, 0x5410);
                    w0.y = __byte_perm(lo.x, hi.x, 0x7632);
                    w0.z = __byte_perm(lo.y, hi.y, 0x5410);
                    w0.w = __byte_perm(lo.y, hi.y, 0x7632);
                    w1.x = __byte_perm(lo.z, hi.z, 0x5410);
                    w1.y = __byte_perm(lo.z, hi.z, 0x7632);
                    w1.z = __byte_perm(lo.w, hi.w, 0x5410);
                    w1.w = __byte_perm(lo.w, hi.w, 0x7632);
                    *(uint4*)&Vp[p*VPSH + 8*c]     = w0;
                    *(uint4*)&Vp[p*VPSH + 8*c + 4] = w1;
                }
            }
            __syncthreads();

            // ---- S = Q @ K^T : per-warp 16x64, fp16 k16 ----
            float s[8][4] = {};
            #pragma unroll
            for (int kt = 0; kt < 8; kt++) {
                unsigned a0 = Qs[(rA    )*QSH + kt*8 + t];
                unsigned a1 = Qs[(rA + 8)*QSH + kt*8 + t];
                unsigned a2 = Qs[(rA    )*QSH + kt*8 + t + 4];
                unsigned a3 = Qs[(rA + 8)*QSH + kt*8 + t + 4];
                #pragma unroll
                for (int nt = 0; nt < 8; nt++) {
                    unsigned b0 = Ks[(nt*8 + g)*KSH + kt*8 + t];
                    unsigned b1 = Ks[(nt*8 + g)*KSH + kt*8 + t + 4];
                    mma_f16(s[nt], a0, a1, a2, a3, b0, b1);
                }
            }

            // ---- causal mask (diagonal band tiles only) ----
            if (j >= 2 * ib) {
                int rowA = qrow0 + rA, rowB = rowA + 8;
                #pragma unroll
                for (int nt = 0; nt < 8; nt++) {
                    int c0 = j*64 + nt*8 + 2*t;
                    if (c0     > rowA) s[nt][0] = -CUDART_INF_F;
                    if (c0 + 1 > rowA) s[nt][1] = -CUDART_INF_F;
                    if (c0     > rowB) s[nt][2] = -CUDART_INF_F;
                    if (c0 + 1 > rowB) s[nt][3] = -CUDART_INF_F;
                }
            }

            // ---- online softmax ----
            float tmA = -CUDART_INF_F, tmB = -CUDART_INF_F;
            #pragma unroll
            for (int nt = 0; nt < 8; nt++) {
                tmA = fmaxf(tmA, fmaxf(s[nt][0], s[nt][1]));
                tmB = fmaxf(tmB, fmaxf(s[nt][2], s[nt][3]));
            }
            tmA = fmaxf(tmA, __shfl_xor_sync(0xffffffffu, tmA, 1));
            tmA = fmaxf(tmA, __shfl_xor_sync(0xffffffffu, tmA, 2));
            tmB = fmaxf(tmB, __shfl_xor_sync(0xffffffffu, tmB, 1));
            tmB = fmaxf(tmB, __shfl_xor_sync(0xffffffffu, tmB, 2));

            float mnA = fmaxf(mA, tmA), mnB = fmaxf(mB, tmB);
            float scA = exp2f(mA - mnA), scB = exp2f(mB - mnB);
            mA = mnA; mB = mnB;

            float rsA = 0.f, rsB = 0.f;
            #pragma unroll
            for (int nt = 0; nt < 8; nt++) {
                float p0 = exp2f(s[nt][0] - mnA);
                float p1 = exp2f(s[nt][1] - mnA);
                float p2 = exp2f(s[nt][2] - mnB);
                float p3 = exp2f(s[nt][3] - mnB);
                rsA += p0 + p1;  rsB += p2 + p3;
                __half2 hA = __floats2half2_rn(p0, p1);   // lo = col 2t
                __half2 hB = __floats2half2_rn(p2, p3);
                Ps[(rA    )*PSH + nt*4 + t] = *(unsigned*)&hA;
                Ps[(rA + 8)*PSH + nt*4 + t] = *(unsigned*)&hB;
            }
            lA = lA * scA + rsA;
            lB = lB * scB + rsB;

            #pragma unroll
            for (int nt = 0; nt < 16; nt++) {
                o[nt][0] *= scA; o[nt][1] *= scA;
                o[nt][2] *= scB; o[nt][3] *= scB;
            }

            __syncwarp();  // P tile is warp-private: writes before fragment reads

            // ---- O += P @ V : per-warp 16x128, fp16 k16 (4 kt over 64 keys) ----
            #pragma unroll
            for (int kt = 0; kt < 4; kt++) {
                unsigned a0 = Ps[(rA    )*PSH + kt*8 + t];
                unsigned a1 = Ps[(rA + 8)*PSH + kt*8 + t];
                unsigned a2 = Ps[(rA    )*PSH + kt*8 + t + 4];
                unsigned a3 = Ps[(rA + 8)*PSH + kt*8 + t + 4];
                #pragma unroll
                for (int nt = 0; nt < 16; nt++) {
                    unsigned b0 = Vp[(kt*8 + t    )*VPSH + nt*8 + g];
                    unsigned b1 = Vp[(kt*8 + t + 4)*VPSH + nt*8 + g];
                    mma_f16(o[nt], a0, a1, a2, a3, b0, b1);
                }
            }
        }

        // ---- write un-normalized partial (O, m, l) ----
        lA += __shfl_xor_sync(0xffffffffu, lA, 1);
        lA += __shfl_xor_sync(0xffffffffu, lA, 2);
        lB += __shfl_xor_sync(0xffffffffu, lB, 1);
        lB += __shfl_xor_sync(0xffffffffu, lB, 2);

        float* PO = g_pO + (size_t)slot * 128 * DHEAD;
        #pragma unroll
        for (int nt = 0; nt < 16; nt++) {
            int c = nt*8 + 2*t;
            float2 v0 = make_float2(o[nt][0], o[nt][1]);
            float2 v1 = make_float2(o[nt][2], o[nt][3]);
            *(float2*)&PO[(size_t)rA * DHEAD + c]       = v0;
            *(float2*)&PO[(size_t)(rA + 8) * DHEAD + c] = v1;
        }
        if (t == 0) {
            g_pm[slot*128 + rA]     = mA;
            g_pm[slot*128 + rA + 8] = mB;
            g_pl[slot*128 + rA]     = lA;
            g_pl[slot*128 + rA + 8] = lB;
        }
    }
}

// ============================================================================
// Combine partials: out = (sum_c 2^(m_c-Mg) O_c) / (sum_c 2^(m_c-Mg) l_c)
// One CTA per (batch, qblock). Also resets the work counter for next replay.
// ============================================================================
__global__ __launch_bounds__(256) void combine_kernel(float* __restrict__ out)
{
    if (blockIdx.x == 0 && threadIdx.x == 0) g_ctr = 0;  // flash already done

    const int b  = blockIdx.x >> 5;
    const int ib = blockIdx.x & 31;
    const int jmax = 2*ib + 2;
    const int n    = (jmax + CHUNK - 1) / CHUNK;
    const int base = (b*32 + ib) << 2;
    const int tid  = threadIdx.x;

    __shared__ float w[4][128];
    __shared__ float invL[128];

    if (tid < 128) {
        float mv[4];
        float Mg = -CUDART_INF_F;
        for (int c = 0; c < n; c++) {
            mv[c] = g_pm[(base + c)*128 + tid];
            Mg = fmaxf(Mg, mv[c]);
        }
        float L = 0.f;
        for (int c = 0; c < n; c++) {
            float wc = exp2f(mv[c] - Mg);
            w[c][tid] = wc;
            L += wc * g_pl[(base + c)*128 + tid];
        }
        invL[tid] = 1.f / L;
    }
    __syncthreads();

    float* O = out + ((size_t)b * SEQ + ib * 128) * DHEAD;
    for (int e = tid; e < 128 * 32; e += 256) {     // float4 granularity
        int r  = e >> 5;
        int c4 = (e & 31) * 4;
        float4 acc = make_float4(0.f, 0.f, 0.f, 0.f);
        for (int c = 0; c < n; c++) {
            const float4 p = *(const float4*)&g_pO[((size_t)(base + c) * 128 + r) * DHEAD + c4];
            float wc = w[c][r];
            acc.x += wc * p.x; acc.y += wc * p.y;
            acc.z += wc * p.z; acc.w += wc * p.w;
        }
        float il = invL[r];
        acc.x *= il; acc.y *= il; acc.z *= il; acc.w *= il;
        *(float4*)&O[(size_t)r * DHEAD + c4] = acc;
    }
}

// ============================================================================
extern "C" void kernel_launch(void* const* d_in, const int* in_sizes, int n_in,
                              void* d_out, int out_size)
{
    const float* q  = (const float*)d_in[0];
    const float* k  = (const float*)d_in[1];
    const float* v  = (const float*)d_in[2];
    const float* wq = (const float*)d_in[3];
    const float* wk = (const float*)d_in[4];
    const float* wv = (const float*)d_in[5];
    float* out = (float*)d_out;

    cudaFuncSetAttribute(flash_kernel,
                         cudaFuncAttributeMaxDynamicSharedMemorySize, FLASH_SMEM);

    proj_kernel<<<dim3(MROWS/128, 1, 3), 256>>>(q, k, v, wq, wk, wv);
    flash_kernel<<<148, 256, FLASH_SMEM>>>();
    combine_kernel<<<BATCH*32, 256>>>(out);
}

// round 16
// speedup vs baseline: 1.8451x; 1.1586x over previous
#include <cuda_runtime.h>
#include <cuda_fp16.h>
#include <math_constants.h>
#include <cstdint>

#define BATCH 4
#define SEQ 4096
#define DMODEL 1024
#define DHEAD 128
#define MROWS (BATCH*SEQ)   // 16384

#define CHUNK 16            // max KV tiles (of 64 keys) per work unit
#define NUNITS 320          // 4 batches * sum_ib ceil((2ib+2)/16) = 4*80
#define NSLOTS 512          // (b*32+ib)*4 + c, c < 4

#define QSCALEF (1.4426950408889634f * 0.08838834764831845f)  // log2e/sqrt(128)

// Scratch (device globals: no allocations allowed).
// Projected Q/K/V stored as fp16 (Q pre-scaled by QSCALEF in proj epilogue).
__device__ __align__(16) __half g_Qh[MROWS*DHEAD];
__device__ __align__(16) __half g_Kh[MROWS*DHEAD];
__device__ __align__(16) __half g_Vh[MROWS*DHEAD];
__device__ float g_pO[NSLOTS*128*DHEAD];   // un-normalized partial O per slot
__device__ float g_pm[NSLOTS*128];         // per-row running max (exp2 domain)
__device__ float g_pl[NSLOTS*128];         // per-row partial denom
__device__ int   g_ctr;                    // persistent-kernel work counter

// fp16 HMMA, f32 accumulate — C layout identical to m16n8k8
__device__ __forceinline__ void mma_f16(float* d,
    unsigned a0, unsigned a1, unsigned a2, unsigned a3,
    unsigned b0, unsigned b1)
{
    asm volatile(
        "mma.sync.aligned.m16n8k16.row.col.f32.f16.f16.f32 "
        "{%0,%1,%2,%3}, {%4,%5,%6,%7}, {%8,%9}, {%0,%1,%2,%3};"
        : "+f"(d[0]), "+f"(d[1]), "+f"(d[2]), "+f"(d[3])
        : "r"(a0), "r"(a1), "r"(a2), "r"(a3), "r"(b0), "r"(b1));
}

__device__ __forceinline__ unsigned h2bits(float a, float b){
    __half2 h = __floats2half2_rn(a, b);
    return *(unsigned*)&h;
}

// ============================================================================
// Projection: Y[16384,128] = X[16384,1024] @ W[128,1024]^T   (fp16 HMMA k16)
// Software-pipelined: K-step 32, double-buffered smem tiles, register-staged
// LDGs for tile it+1 issued before the MMA loop of tile it, ONE barrier/iter.
// Smem word (r,c) = halfs (2c,2c+1) of row r; stride 20 words (conflict-free:
// 20g mod 32 = {0,20,8,28,16,4,24,12}).
// ============================================================================
#define PJSH 20
#define PJT (128*PJSH)      // words per tile (X or W), 2560

__global__ __launch_bounds__(256, 2) void proj_kernel(
    const float* __restrict__ q, const float* __restrict__ k, const float* __restrict__ v,
    const float* __restrict__ wq, const float* __restrict__ wk, const float* __restrict__ wv)
{
    __shared__ unsigned Xs[2][PJT];
    __shared__ unsigned Ws[2][PJT];

    const float* X; const float* W; __half* Y;
    if (blockIdx.z == 0)      { X = q; W = wq; Y = g_Qh; }
    else if (blockIdx.z == 1) { X = k; W = wk; Y = g_Kh; }
    else                      { X = v; W = wv; Y = g_Vh; }

    const int row0 = blockIdx.x * 128;
    const int tid  = threadIdx.x;
    const int wid  = tid >> 5;
    const int lane = tid & 31;
    const int g    = lane >> 2;
    const int t    = lane & 3;
    const int wr   = (wid >> 1) * 32;
    const int wc   = (wid & 1) * 64;

    // Staging coords: 4 float4 of X + 4 of W per tile (32-col K-step)
    const int sr = tid >> 3;          // row within 0..31 block (+i*32)
    const int sc = (tid & 7) * 4;     // float column 0..28

    float4 xr[4], wr4[4];

    // prologue: tile 0
    #pragma unroll
    for (int i = 0; i < 4; i++) {
        int r = sr + i*32;
        xr[i]  = *(const float4*)&X[(size_t)(row0 + r) * DMODEL + sc];
        wr4[i] = *(const float4*)&W[(size_t)r * DMODEL + sc];
    }
    #pragma unroll
    for (int i = 0; i < 4; i++) {
        int r = sr + i*32;
        uint2 xw = { h2bits(xr[i].x,  xr[i].y),  h2bits(xr[i].z,  xr[i].w)  };
        uint2 ww = { h2bits(wr4[i].x, wr4[i].y), h2bits(wr4[i].z, wr4[i].w) };
        *(uint2*)&Xs[0][r*PJSH + (sc>>1)] = xw;
        *(uint2*)&Ws[0][r*PJSH + (sc>>1)] = ww;
    }
    __syncthreads();

    float acc[2][8][4] = {};

    #pragma unroll 1
    for (int it = 0; it < DMODEL/32; it++) {
        const int cur = it & 1, nxt = cur ^ 1;

        // issue next tile's LDGs now — latency hidden under MMAs
        if (it + 1 < DMODEL/32) {
            const int k0 = (it + 1) * 32;
            #pragma unroll
            for (int i = 0; i < 4; i++) {
                int r = sr + i*32;
                xr[i]  = *(const float4*)&X[(size_t)(row0 + r) * DMODEL + k0 + sc];
                wr4[i] = *(const float4*)&W[(size_t)r * DMODEL + k0 + sc];
            }
        }

        // MMAs on current buffer: 2 x k16 over the 32-wide tile
        const unsigned* Xc = Xs[cur];
        const unsigned* Wc = Ws[cur];
        #pragma unroll
        for (int kt = 0; kt < 2; kt++) {
            unsigned a[2][4];
            #pragma unroll
            for (int mt = 0; mt < 2; mt++) {
                int r = wr + mt * 16;
                a[mt][0] = Xc[(r + g    )*PJSH + kt*8 + t];
                a[mt][1] = Xc[(r + g + 8)*PJSH + kt*8 + t];
                a[mt][2] = Xc[(r + g    )*PJSH + kt*8 + t + 4];
                a[mt][3] = Xc[(r + g + 8)*PJSH + kt*8 + t + 4];
            }
            #pragma unroll
            for (int nt = 0; nt < 8; nt++) {
                unsigned b0 = Wc[(wc + nt*8 + g)*PJSH + kt*8 + t];
                unsigned b1 = Wc[(wc + nt*8 + g)*PJSH + kt*8 + t + 4];
                mma_f16(acc[0][nt], a[0][0], a[0][1], a[0][2], a[0][3], b0, b1);
                mma_f16(acc[1][nt], a[1][0], a[1][1], a[1][2], a[1][3], b0, b1);
            }
        }

        // convert + store staged regs into the other buffer
        if (it + 1 < DMODEL/32) {
            #pragma unroll
            for (int i = 0; i < 4; i++) {
                int r = sr + i*32;
                uint2 xw = { h2bits(xr[i].x,  xr[i].y),  h2bits(xr[i].z,  xr[i].w)  };
                uint2 ww = { h2bits(wr4[i].x, wr4[i].y), h2bits(wr4[i].z, wr4[i].w) };
                *(uint2*)&Xs[nxt][r*PJSH + (sc>>1)] = xw;
                *(uint2*)&Ws[nxt][r*PJSH + (sc>>1)] = ww;
            }
        }
        __syncthreads();   // nxt-buffer STS visible; cur-buffer reads done
    }

    const float scale = (blockIdx.z == 0) ? QSCALEF : 1.0f;
    #pragma unroll
    for (int mt = 0; mt < 2; mt++) {
        int r = row0 + wr + mt*16 + g;
        #pragma unroll
        for (int nt = 0; nt < 8; nt++) {
            int c = wc + nt*8 + 2*t;
            __half2 v0 = __floats2half2_rn(acc[mt][nt][0]*scale, acc[mt][nt][1]*scale);
            __half2 v1 = __floats2half2_rn(acc[mt][nt][2]*scale, acc[mt][nt][3]*scale);
            *(__half2*)&Y[(size_t)r * DHEAD + c]       = v0;
            *(__half2*)&Y[(size_t)(r + 8) * DHEAD + c] = v1;
        }
    }
}

// ============================================================================
// Split-KV flash attention, causal, fp16 MMA (m16n8k16).  [unchanged from R14]
// Smem layouts (4B words):
//   Qs: 128 x 68   word (r,c) = halfs (2c,2c+1) of Q row r
//   Ks: 64  x 68   same layout for K
//   Vp: 32  x 132  word (p,n) = half2( V[2p][n], V[2p+1][n] )  (key pairs)
//   Ps: 128 x 36   word (r,c) = half2( P[r][2c], P[r][2c+1] )
// ============================================================================
#define QSH 68
#define KSH 68
#define VPSH 132
#define PSH 36
#define QWsz (128*QSH)    // 8704 words
#define KWsz (64*KSH)     // 4352
#define VWsz (32*VPSH)    // 4224
#define PWsz (128*PSH)    // 4608
#define FLASH_SMEM ((QWsz + KWsz + VWsz + PWsz) * 4)   // 87552 B

__device__ __forceinline__ void decode_unit(int u, int& b, int& ib,
                                            int& j0, int& j1, int& slot)
{
    b = u & 3;
    int v = u >> 2;              // 0..79, descending-ib order (big units first)
    int acc = 0, ibb = 0, n = 1;
    #pragma unroll 1
    for (int i = 31; i >= 0; --i) {
        int jm = 2*i + 2;
        int ni = (jm + CHUNK - 1) / CHUNK;
        if (v < acc + ni) { ibb = i; n = ni; break; }
        acc += ni;
    }
    int c    = v - acc;
    int jmax = 2*ibb + 2;
    int len  = (jmax + n - 1) / n;
    j0 = c * len;
    j1 = min(jmax, j0 + len);
    ib = ibb;
    slot = ((b*32 + ibb) << 2) + c;
}

__global__ __launch_bounds__(256, 1) void flash_kernel()
{
    extern __shared__ unsigned sm[];
    unsigned* Qs = sm;
    unsigned* Ks = Qs + QWsz;
    unsigned* Vp = Ks + KWsz;
    unsigned* Ps = Vp + VWsz;
    __shared__ int s_unit;

    const int tid  = threadIdx.x;
    const int wid  = tid >> 5;
    const int lane = tid & 31;
    const int g    = lane >> 2;
    const int t    = lane & 3;
    const int rA   = wid * 16 + g;   // local row (and rA+8)

    for (;;) {
        if (tid == 0) s_unit = atomicAdd(&g_ctr, 1);
        __syncthreads();             // broadcast; also fences prior unit's smem reads
        int u = s_unit;
        if (u >= NUNITS) break;

        int b, ib, j0, j1, slot;
        decode_unit(u, b, ib, j0, j1, slot);
        const int qrow0 = ib * 128;
        const __half* Qg = g_Qh + (size_t)b * SEQ * DHEAD;
        const __half* Kg = g_Kh + (size_t)b * SEQ * DHEAD;
        const __half* Vg = g_Vh + (size_t)b * SEQ * DHEAD;

        // ---- stage Q tile: 128x128 fp16, 2048 uint4, coalesced ----
        {
            const uint4* Q4 = (const uint4*)(Qg + (size_t)qrow0 * DHEAD);
            #pragma unroll
            for (int i = 0; i < 8; i++) {
                int e = tid + i * 256;
                int r = e >> 4, c = e & 15;
                *(uint4*)&Qs[r*QSH + 4*c] = Q4[e];
            }
        }

        float o[16][4] = {};
        float mA = -CUDART_INF_F, mB = -CUDART_INF_F;
        float lA = 0.f, lB = 0.f;

        for (int j = j0; j < j1; j++) {
            __syncthreads();   // prev tile's reads done (also orders Q staging)
            {
                // K tile: 64x128 fp16, 1024 uint4
                const uint4* K4 = (const uint4*)(Kg + (size_t)j * 64 * DHEAD);
                #pragma unroll
                for (int i = 0; i < 4; i++) {
                    int e = tid + i * 256;
                    int r = e >> 4, c = e & 15;
                    *(uint4*)&Ks[r*KSH + 4*c] = K4[e];
                }
                // V tile: pair-interleave keys (2p,2p+1) -> Vp[p][dim]
                const uint4* V4 = (const uint4*)(Vg + (size_t)j * 64 * DHEAD);
                #pragma unroll
                for (int i = 0; i < 2; i++) {
                    int e = tid + i * 256;          // pair-unit id, 0..511
                    int p = e >> 4, c = e & 15;     // pair row, uint4 col (8 dims)
                    uint4 lo = V4[(2*p    )*16 + c];
                    uint4 hi = V4[(2*p + 1)*16 + c];
                    uint4 w0, w1;
                    w0.x = __byte_perm(lo.x, hi.x, 0x5410);
                    w0.y = __byte_perm(lo.x, hi.x, 0x7632);
                    w0.z = __byte_perm(lo.y, hi.y, 0x5410);
                    w0.w = __byte_perm(lo.y, hi.y, 0x7632);
                    w1.x = __byte_perm(lo.z, hi.z, 0x5410);
                    w1.y = __byte_perm(lo.z, hi.z, 0x7632);
                    w1.z = __byte_perm(lo.w, hi.w, 0x5410);
                    w1.w = __byte_perm(lo.w, hi.w, 0x7632);
                    *(uint4*)&Vp[p*VPSH + 8*c]     = w0;
                    *(uint4*)&Vp[p*VPSH + 8*c + 4] = w1;
                }
            }
            __syncthreads();

            // ---- S = Q @ K^T : per-warp 16x64, fp16 k16 ----
            float s[8][4] = {};
            #pragma unroll
            for (int kt = 0; kt < 8; kt++) {
                unsigned a0 = Qs[(rA    )*QSH + kt*8 + t];
                unsigned a1 = Qs[(rA + 8)*QSH + kt*8 + t];
                unsigned a2 = Qs[(rA    )*QSH + kt*8 + t + 4];
                unsigned a3 = Qs[(rA + 8)*QSH + kt*8 + t + 4];
                #pragma unroll
                for (int nt = 0; nt < 8; nt++) {
                    unsigned b0 = Ks[(nt*8 + g)*KSH + kt*8 + t];
                    unsigned b1 = Ks[(nt*8 + g)*KSH + kt*8 + t + 4];
                    mma_f16(s[nt], a0, a1, a2, a3, b0, b1);
                }
            }

            // ---- causal mask (diagonal band tiles only) ----
            if (j >= 2 * ib) {
                int rowA = qrow0 + rA, rowB = rowA + 8;
                #pragma unroll
                for (int nt = 0; nt < 8; nt++) {
                    int c0 = j*64 + nt*8 + 2*t;
                    if (c0     > rowA) s[nt][0] = -CUDART_INF_F;
                    if (c0 + 1 > rowA) s[nt][1] = -CUDART_INF_F;
                    if (c0     > rowB) s[nt][2] = -CUDART_INF_F;
                    if (c0 + 1 > rowB) s[nt][3] = -CUDART_INF_F;
                }
            }

            // ---- online softmax ----
            float tmA = -CUDART_INF_F, tmB = -CUDART_INF_F;
            #pragma unroll
            for (int nt = 0; nt < 8; nt++) {
                tmA = fmaxf(tmA, fmaxf(s[nt][0], s[nt][1]));
                tmB = fmaxf(tmB, fmaxf(s[nt][2], s[nt][3]));
            }
            tmA = fmaxf(tmA, __shfl_xor_sync(0xffffffffu, tmA, 1));
            tmA = fmaxf(tmA, __shfl_xor_sync(0xffffffffu, tmA, 2));
            tmB = fmaxf(tmB, __shfl_xor_sync(0xffffffffu, tmB, 1));
            tmB = fmaxf(tmB, __shfl_xor_sync(0xffffffffu, tmB, 2));

            float mnA = fmaxf(mA, tmA), mnB = fmaxf(mB, tmB);
            float scA = exp2f(mA - mnA), scB = exp2f(mB - mnB);
            mA = mnA; mB = mnB;

            float rsA = 0.f, rsB = 0.f;
            #pragma unroll
            for (int nt = 0; nt < 8; nt++) {
                float p0 = exp2f(s[nt][0] - mnA);
                float p1 = exp2f(s[nt][1] - mnA);
                float p2 = exp2f(s[nt][2] - mnB);
                float p3 = exp2f(s[nt][3] - mnB);
                rsA += p0 + p1;  rsB += p2 + p3;
                __half2 hA = __floats2half2_rn(p0, p1);   // lo = col 2t
                __half2 hB = __floats2half2_rn(p2, p3);
                Ps[(rA    )*PSH + nt*4 + t] = *(unsigned*)&hA;
                Ps[(rA + 8)*PSH + nt*4 + t] = *(unsigned*)&hB;
            }
            lA = lA * scA + rsA;
            lB = lB * scB + rsB;

            #pragma unroll
            for (int nt = 0; nt < 16; nt++) {
                o[nt][0] *= scA; o[nt][1] *= scA;
                o[nt][2] *= scB; o[nt][3] *= scB;
            }

            __syncwarp();  // P tile is warp-private: writes before fragment reads

            // ---- O += P @ V : per-warp 16x128, fp16 k16 (4 kt over 64 keys) ----
            #pragma unroll
            for (int kt = 0; kt < 4; kt++) {
                unsigned a0 = Ps[(rA    )*PSH + kt*8 + t];
                unsigned a1 = Ps[(rA + 8)*PSH + kt*8 + t];
                unsigned a2 = Ps[(rA    )*PSH + kt*8 + t + 4];
                unsigned a3 = Ps[(rA + 8)*PSH + kt*8 + t + 4];
                #pragma unroll
                for (int nt = 0; nt < 16; nt++) {
                    unsigned b0 = Vp[(kt*8 + t    )*VPSH + nt*8 + g];
                    unsigned b1 = Vp[(kt*8 + t + 4)*VPSH + nt*8 + g];
                    mma_f16(o[nt], a0, a1, a2, a3, b0, b1);
                }
            }
        }

        // ---- write un-normalized partial (O, m, l) ----
        lA += __shfl_xor_sync(0xffffffffu, lA, 1);
        lA += __shfl_xor_sync(0xffffffffu, lA, 2);
        lB += __shfl_xor_sync(0xffffffffu, lB, 1);
        lB += __shfl_xor_sync(0xffffffffu, lB, 2);

        float* PO = g_pO + (size_t)slot * 128 * DHEAD;
        #pragma unroll
        for (int nt = 0; nt < 16; nt++) {
            int c = nt*8 + 2*t;
            float2 v0 = make_float2(o[nt][0], o[nt][1]);
            float2 v1 = make_float2(o[nt][2], o[nt][3]);
            *(float2*)&PO[(size_t)rA * DHEAD + c]       = v0;
            *(float2*)&PO[(size_t)(rA + 8) * DHEAD + c] = v1;
        }
        if (t == 0) {
            g_pm[slot*128 + rA]     = mA;
            g_pm[slot*128 + rA + 8] = mB;
            g_pl[slot*128 + rA]     = lA;
            g_pl[slot*128 + rA + 8] = lB;
        }
    }
}

// ============================================================================
// Combine partials: out = (sum_c 2^(m_c-Mg) O_c) / (sum_c 2^(m_c-Mg) l_c)
// One CTA per (batch, qblock). Also resets the work counter for next replay.
// ============================================================================
__global__ __launch_bounds__(256) void combine_kernel(float* __restrict__ out)
{
    if (blockIdx.x == 0 && threadIdx.x == 0) g_ctr = 0;  // flash already done

    const int b  = blockIdx.x >> 5;
    const int ib = blockIdx.x & 31;
    const int jmax = 2*ib + 2;
    const int n    = (jmax + CHUNK - 1) / CHUNK;
    const int base = (b*32 + ib) << 2;
    const int tid  = threadIdx.x;

    __shared__ float w[4][128];
    __shared__ float invL[128];

    if (tid < 128) {
        float mv[4];
        float Mg = -CUDART_INF_F;
        for (int c = 0; c < n; c++) {
            mv[c] = g_pm[(base + c)*128 + tid];
            Mg = fmaxf(Mg, mv[c]);
        }
        float L = 0.f;
        for (int c = 0; c < n; c++) {
            float wc = exp2f(mv[c] - Mg);
            w[c][tid] = wc;
            L += wc * g_pl[(base + c)*128 + tid];
        }
        invL[tid] = 1.f / L;
    }
    __syncthreads();

    float* O = out + ((size_t)b * SEQ + ib * 128) * DHEAD;
    for (int e = tid; e < 128 * 32; e += 256) {     // float4 granularity
        int r  = e >> 5;
        int c4 = (e & 31) * 4;
        float4 acc = make_float4(0.f, 0.f, 0.f, 0.f);
        for (int c = 0; c < n; c++) {
            const float4 p = *(const float4*)&g_pO[((size_t)(base + c) * 128 + r) * DHEAD + c4];
            float wc = w[c][r];
            acc.x += wc * p.x; acc.y += wc * p.y;
            acc.z += wc * p.z; acc.w += wc * p.w;
        }
        float il = invL[r];
        acc.x *= il; acc.y *= il; acc.z *= il; acc.w *= il;
        *(float4*)&O[(size_t)r * DHEAD + c4] = acc;
    }
}

// ============================================================================
extern "C" void kernel_launch(void* const* d_in, const int* in_sizes, int n_in,
                              void* d_out, int out_size)
{
    const float* q  = (const float*)d_in[0];
    const float* k  = (const float*)d_in[1];
    const float* v  = (const float*)d_in[2];
    const float* wq = (const float*)d_in[3];
    const float* wk = (const float*)d_in[4];
    const float* wv = (const float*)d_in[5];
    float* out = (float*)d_out;

    cudaFuncSetAttribute(flash_kernel,
                         cudaFuncAttributeMaxDynamicSharedMemorySize, FLASH_SMEM);

    proj_kernel<<<dim3(MROWS/128, 1, 3), 256>>>(q, k, v, wq, wk, wv);
    flash_kernel<<<148, 256, FLASH_SMEM>>>();
    combine_kernel<<<BATCH*32, 256>>>(out);
}